// round 14
// baseline (speedup 1.0000x reference)
#include <cuda_runtime.h>
#include <stdint.h>

#define NC 4096   // concepts (= output cols)
#define CD 1024   // cdim
#define BT 4096   // batch rows
#define KS 256    // sampled per row

#define K1_CTAS   2048
#define ZERO_CTAS 1536                       // bids with (bid & 3) != 0
#define TOTAL_V8  ((BT * NC) / 8)            // 2M 32B-units
#define ZSTRIDE   (ZERO_CTAS * 256)
#define SCAT_CTAS ((BT * KS / 4) / 256)      // 1024

// Scratch (allocation-free rule: device global).
__device__ float g_s[NC];   // 16 KB

// ---------------------------------------------------------------------------
// Kernel 1: role-interleaved CTA specialization.
//   (bid & 3) == 0 : dot CTA  — 8 warps, 8 concept rows -> g_s  (READ stream)
//   (bid & 3) != 0 : zero CTA — grid-stride 32B zerofill of out (WRITE stream)
// Interleaving by bid keeps every scheduling wave ~25% readers / 75% writers,
// so the 36MB read stream hides under the 64MiB write wall instead of running
// in a separate wave (the R11/R12 failure mode).
// ---------------------------------------------------------------------------
__global__ __launch_bounds__(256) void dotzero_kernel(
    const float* __restrict__ cb, const float* __restrict__ attn,
    float* __restrict__ out)
{
    const int t   = threadIdx.x;
    const int bid = blockIdx.x;

    if ((bid & 3) == 0) {
        // ---- dot CTA: did in [0,512) ----
        const int did  = bid >> 2;
        const int warp = t >> 5;
        const int lane = t & 31;
        const int row  = did * 8 + warp;

        const float4* c4 = reinterpret_cast<const float4*>(cb   + (size_t)row * CD);
        const float4* a4 = reinterpret_cast<const float4*>(attn + (size_t)row * CD);

        float4 c[8], a[8];
        #pragma unroll
        for (int i = 0; i < 8; i++) c[i] = c4[lane + i * 32];
        #pragma unroll
        for (int i = 0; i < 8; i++) a[i] = a4[lane + i * 32];

        float sum = 0.f;
        #pragma unroll
        for (int i = 0; i < 8; i++)
            sum += c[i].x * a[i].x + c[i].y * a[i].y
                 + c[i].z * a[i].z + c[i].w * a[i].w;

        #pragma unroll
        for (int o = 16; o > 0; o >>= 1)
            sum += __shfl_xor_sync(0xFFFFFFFFu, sum, o);
        if (lane == 0) g_s[row] = sum;
    } else {
        // ---- zero CTA: zid in [0,1536) dense, coalesced v8 stores ----
        const int zid = bid - (bid >> 2) - 1;
        float* p = out + (size_t)(zid * 256 + t) * 8;
        const size_t step = (size_t)ZSTRIDE * 8;
        #pragma unroll 1
        for (int i = zid * 256 + t; i < TOTAL_V8; i += ZSTRIDE, p += step) {
            asm volatile(
                "st.global.v8.f32 [%0], {%1,%1,%1,%1,%1,%1,%1,%1};"
                :: "l"(p), "f"(0.f) : "memory");
        }
    }
}

// ---------------------------------------------------------------------------
// Kernel 2 (PDL): sparse scatter of the 1M nonzeros into L2-hot zeroed lines.
// out[b, idx[b,k]] = s[idx[b,k]]; duplicates write equal values (benign).
// ---------------------------------------------------------------------------
__global__ __launch_bounds__(256) void scatter_kernel(
    const int* __restrict__ idx, float* __restrict__ out)
{
#if (__CUDACC_VER_MAJOR__ >= 12)
    cudaGridDependencySynchronize();     // K1 writes visible before we start
#endif
    const int gtid = blockIdx.x * 256 + threadIdx.x;   // 262144 threads
    const int4 v   = reinterpret_cast<const int4*>(idx)[gtid];
    const int  b   = gtid >> 6;                        // 64 int4 per row (KS=256)
    float* orow    = out + (size_t)b * NC;

    const int a0 = v.x & (NC - 1), a1 = v.y & (NC - 1);
    const int a2 = v.z & (NC - 1), a3 = v.w & (NC - 1);
    orow[a0] = g_s[a0];
    orow[a1] = g_s[a1];
    orow[a2] = g_s[a2];
    orow[a3] = g_s[a3];
}

extern "C" void kernel_launch(void* const* d_in, const int* in_sizes, int n_in,
                              void* d_out, int out_size)
{
    const float* cb   = (const float*)d_in[0];
    const float* attn = (const float*)d_in[1];
    const int*   idx  = (const int*)d_in[2];
    float*       out  = (float*)d_out;

    dotzero_kernel<<<K1_CTAS, 256>>>(cb, attn, out);

    cudaLaunchConfig_t cfg = {};
    cfg.gridDim  = dim3(SCAT_CTAS, 1, 1);
    cfg.blockDim = dim3(256, 1, 1);
    cudaLaunchAttribute attrs[1];
    attrs[0].id = cudaLaunchAttributeProgrammaticStreamSerialization;
    attrs[0].val.programmaticStreamSerializationAllowed = 1;
    cfg.attrs = attrs;
    cfg.numAttrs = 1;
    cudaLaunchKernelEx(&cfg, scatter_kernel, idx, out);
}

// round 15
// speedup vs baseline: 1.0508x; 1.0508x over previous
#include <cuda_runtime.h>
#include <stdint.h>

#define NC 4096   // concepts (= output cols)
#define CD 1024   // cdim
#define BT 4096   // batch rows
#define KS 256    // sampled per row

// Scratch (allocation-free rule: device globals).
__device__ float    g_s[NC];                  // 16 KB
__device__ unsigned g_mask[BT * (NC / 32)];   // 2 MB, 128 words/row

// ---------------------------------------------------------------------------
// Kernel 1 (prep): 1024 CTAs. Per CTA:
//   - masks for 4 batch rows (1024 indices = 1 int4/thread, shared atomicOr)
//   - dots for 4 concept rows, TWO warps per row (half-row each, 8 batched
//     LDG.128 per warp) -> 8192 warps chip-wide, 2x the outstanding loads of
//     the old 1-warp-per-row prep.
// ---------------------------------------------------------------------------
__global__ __launch_bounds__(256) void prep_kernel(
    const float* __restrict__ cb, const float* __restrict__ attn,
    const int* __restrict__ sampled_idx)
{
    __shared__ unsigned bm[4 * 128];   // 2 KB
    __shared__ float    partial[8];

    const int t    = threadIdx.x;
    const int warp = t >> 5;
    const int lane = t & 31;
    const int bid  = blockIdx.x;

    if (t < 128) reinterpret_cast<uint4*>(bm)[t] = make_uint4(0u, 0u, 0u, 0u);
    __syncthreads();

    // Masks: 4 rows x 256 idx = 256 int4, one per thread. Row = t>>6.
    {
        const int4* i4 = reinterpret_cast<const int4*>(
            sampled_idx + (size_t)bid * 4 * KS);
        int4 v = i4[t];
        const int r = t >> 6;
        int a = v.x & (NC - 1), b = v.y & (NC - 1);
        int c = v.z & (NC - 1), d = v.w & (NC - 1);
        atomicOr(&bm[r * 128 + (a >> 5)], 1u << (a & 31));
        atomicOr(&bm[r * 128 + (b >> 5)], 1u << (b & 31));
        atomicOr(&bm[r * 128 + (c >> 5)], 1u << (c & 31));
        atomicOr(&bm[r * 128 + (d >> 5)], 1u << (d & 31));
    }

    // Dots: warp pair (2w, 2w+1) -> concept row bid*4 + w; half-row each.
    {
        const int row  = bid * 4 + (warp >> 1);
        const int half = warp & 1;
        const float4* c4 = reinterpret_cast<const float4*>(cb   + (size_t)row * CD)
                         + half * 128;
        const float4* a4 = reinterpret_cast<const float4*>(attn + (size_t)row * CD)
                         + half * 128;
        float4 c[4], a[4];
        #pragma unroll
        for (int i = 0; i < 4; i++) c[i] = c4[lane + i * 32];
        #pragma unroll
        for (int i = 0; i < 4; i++) a[i] = a4[lane + i * 32];
        float sum = 0.f;
        #pragma unroll
        for (int i = 0; i < 4; i++)
            sum += c[i].x * a[i].x + c[i].y * a[i].y
                 + c[i].z * a[i].z + c[i].w * a[i].w;
        #pragma unroll
        for (int o = 16; o > 0; o >>= 1)
            sum += __shfl_xor_sync(0xFFFFFFFFu, sum, o);
        if (lane == 0) partial[warp] = sum;
    }
    __syncthreads();   // partials + mask atomics complete

    if (t < 4) g_s[bid * 4 + t] = partial[2 * t] + partial[2 * t + 1];

    // Mask writeout: 512 words = 128 uint4.
    if (t < 128)
        reinterpret_cast<uint4*>(g_mask + (size_t)bid * 512)[t] =
            reinterpret_cast<const uint4*>(bm)[t];
}

// ---------------------------------------------------------------------------
// Kernel 2 (store, PDL): stripe geometry. CTA = 1024 cols x 16 batch rows;
// grid = 4 stripes x 256 row-groups. Thread t: ONE float4 of s (reused for
// all 16 rows -> s-traffic 4MB total), 16 broadcast mask words, 16
// independent STG.128. No shared, no atomics, no barriers.
// ---------------------------------------------------------------------------
__global__ __launch_bounds__(256) void store_kernel(float* __restrict__ out)
{
#if (__CUDACC_VER_MAJOR__ >= 12)
    cudaGridDependencySynchronize();
#endif
    const int t      = threadIdx.x;
    const int stripe = blockIdx.x & 3;
    const int r0     = (blockIdx.x >> 2) * 16;

    const int col4  = stripe * 256 + t;           // float4 index within a row
    const float4 sv = reinterpret_cast<const float4*>(g_s)[col4];
    const int word  = col4 >> 3;                  // 8 float4 per mask word
    const int sh    = (col4 & 7) * 4;

    unsigned w[16];
    #pragma unroll
    for (int r = 0; r < 16; r++)
        w[r] = g_mask[(size_t)(r0 + r) * 128 + word];   // 8-thread broadcast

    float4* o4 = reinterpret_cast<float4*>(out) + (size_t)r0 * 1024 + col4;
    #pragma unroll
    for (int r = 0; r < 16; r++) {
        unsigned b = w[r] >> sh;
        float4 v;
        v.x = (b & 1u) ? sv.x : 0.f;
        v.y = (b & 2u) ? sv.y : 0.f;
        v.z = (b & 4u) ? sv.z : 0.f;
        v.w = (b & 8u) ? sv.w : 0.f;
        o4[(size_t)r * 1024] = v;
    }
}

extern "C" void kernel_launch(void* const* d_in, const int* in_sizes, int n_in,
                              void* d_out, int out_size)
{
    const float* cb   = (const float*)d_in[0];
    const float* attn = (const float*)d_in[1];
    const int*   idx  = (const int*)d_in[2];
    float*       out  = (float*)d_out;

    prep_kernel<<<1024, 256>>>(cb, attn, idx);

    cudaLaunchConfig_t cfg = {};
    cfg.gridDim  = dim3(1024, 1, 1);
    cfg.blockDim = dim3(256, 1, 1);
    cudaLaunchAttribute attrs[1];
    attrs[0].id = cudaLaunchAttributeProgrammaticStreamSerialization;
    attrs[0].val.programmaticStreamSerializationAllowed = 1;
    cfg.attrs = attrs;
    cfg.numAttrs = 1;
    cudaLaunchKernelEx(&cfg, store_kernel, out);
}